// round 3
// baseline (speedup 1.0000x reference)
#include <cuda_runtime.h>
#include <math.h>
#include <stddef.h>

// B=256, T=512, V=64(65 rows), E=128, H=256, 3H=768, D=2

// ---------------- static scratch ----------------
__device__ float d_ptab [2*65*768];
__device__ float d_hping[2*2*256*256];
__device__ float d_h1   [512*256*512];
__device__ float d_xp1  [2*512*256*768];
__device__ float d_h2   [512*256*512];
__device__ float d_fc1p [512*256*128];
__device__ float d_W1t  [262144*128];
__device__ unsigned d_bar_cnt;
__device__ unsigned d_bar_phase;

__global__ void reset_bar_kernel() { d_bar_cnt = 0u; d_bar_phase = 0u; }

// ---------------- grid barrier (128 co-resident CTAs) ----------------
__device__ __forceinline__ void grid_barrier(unsigned target) {
    __syncthreads();
    if (threadIdx.x == 0) {
        __threadfence();
        unsigned arr = atomicAdd(&d_bar_cnt, 1u);
        if (arr == target * 128u - 1u) {
            atomicExch(&d_bar_phase, target);
        } else {
            while (*((volatile unsigned*)&d_bar_phase) < target) { __nanosleep(32); }
            __threadfence();
        }
    }
    __syncthreads();
}

// ---------------- L0 proj table: ptab[d][v][g] = b_ih + emb[v].w_ih[d][g] ----------------
__global__ void __launch_bounds__(256) proj0_kernel(const float* __restrict__ emb,
                                                    const float* __restrict__ wih,
                                                    const float* __restrict__ bih) {
    const int d = blockIdx.x / 65;
    const int v = blockIdx.x % 65;
    __shared__ float es[128];
    if (threadIdx.x < 128) es[threadIdx.x] = emb[v*128 + threadIdx.x];
    __syncthreads();
    for (int g = threadIdx.x; g < 768; g += 256) {
        const float* w = wih + ((size_t)d*768 + g)*128;
        float s = bih[d*768 + g];
        #pragma unroll 4
        for (int e = 0; e < 128; e++) s += es[e]*__ldg(w + e);
        d_ptab[((size_t)d*65 + v)*768 + g] = s;
    }
}

// ---------------- recurrence (both layers) ----------------
// 128 CTAs = dir(2) x batch-slice(8 x 32b) x gate-slice(8 x 32 units)
#define REC_SMEM 131072

template<int LAYER>
__global__ void __launch_bounds__(256, 1) rec_kernel(
    const int* __restrict__ inputs,
    const float* __restrict__ w_hh,
    const float* __restrict__ b_hh) {
    extern __shared__ float smem[];
    float* ws = smem;              // [g*256+k][32 j]  (3*256*32)
    float* hs = smem + 3*256*32;   // [32 b][256 k]
    __shared__ float bhh_s[96];

    const int bid = blockIdx.x;
    const int dir = bid >> 6;
    const int rem = bid & 63;
    const int b0  = (rem >> 3) * 32;
    const int g0  = (rem & 7) * 32;
    const int tid = threadIdx.x;
    const int wq  = tid >> 5;
    const int j   = tid & 31;

    for (int row = wq; row < 96; row += 8) {
        const int g  = row >> 5;
        const int jr = row & 31;
        const float* src = w_hh + ((size_t)dir*768 + g*256 + g0 + jr)*256;
        for (int k = j; k < 256; k += 32)
            ws[(g*256 + k)*32 + jr] = src[k];
    }
    if (tid < 96) bhh_s[tid] = b_hh[dir*768 + (tid>>5)*256 + g0 + (tid&31)];
    __syncthreads();

    for (int s_ = 0; s_ < 512; s_++) {
        const int parity = s_ & 1;
        if (s_ == 0) {
            #pragma unroll
            for (int q = 0; q < 8; q++)
                *(float4*)&hs[(tid + q*256)*4] = make_float4(0.f,0.f,0.f,0.f);
        } else {
            const float4* src = (const float4*)(d_hping + (((size_t)dir*2 + parity)*256 + b0)*256);
            #pragma unroll
            for (int q = 0; q < 8; q++) {
                int fid = tid + q*256;
                float4 v = __ldcg(src + fid);
                *(float4*)&hs[fid*4] = v;
            }
        }
        __syncthreads();

        float ra[4] = {0,0,0,0}, za[4] = {0,0,0,0}, na[4] = {0,0,0,0};
        const float* h0p = hs + (wq*4+0)*256;
        const float* h1p = hs + (wq*4+1)*256;
        const float* h2p = hs + (wq*4+2)*256;
        const float* h3p = hs + (wq*4+3)*256;
        #pragma unroll 4
        for (int k = 0; k < 256; k += 4) {
            float4 v0 = *(const float4*)(h0p + k);
            float4 v1 = *(const float4*)(h1p + k);
            float4 v2 = *(const float4*)(h2p + k);
            float4 v3 = *(const float4*)(h3p + k);
            float hh[4][4] = {
                {v0.x, v1.x, v2.x, v3.x},
                {v0.y, v1.y, v2.y, v3.y},
                {v0.z, v1.z, v2.z, v3.z},
                {v0.w, v1.w, v2.w, v3.w}};
            #pragma unroll
            for (int kk = 0; kk < 4; kk++) {
                float wr = ws[(0*256 + k + kk)*32 + j];
                float wz = ws[(1*256 + k + kk)*32 + j];
                float wn = ws[(2*256 + k + kk)*32 + j];
                #pragma unroll
                for (int i = 0; i < 4; i++) {
                    ra[i] += hh[kk][i] * wr;
                    za[i] += hh[kk][i] * wz;
                    na[i] += hh[kk][i] * wn;
                }
            }
        }

        const int t_in = (dir == 0) ? s_ : (511 - s_);
        float* outbuf = (LAYER == 0) ? d_h1 : d_h2;
        #pragma unroll
        for (int i = 0; i < 4; i++) {
            const int b = b0 + wq*4 + i;
            float xr, xz, xn;
            if (LAYER == 0) {
                const int tok = __ldg(inputs + b*512 + t_in);
                const float* pt = d_ptab + ((size_t)dir*65 + tok)*768;
                xr = __ldg(pt +       g0 + j);
                xz = __ldg(pt + 256 + g0 + j);
                xn = __ldg(pt + 512 + g0 + j);
            } else {
                const float* xp = d_xp1 + ((size_t)dir*131072 + (size_t)t_in*256 + b)*768;
                xr = __ldg(xp +       g0 + j);
                xz = __ldg(xp + 256 + g0 + j);
                xn = __ldg(xp + 512 + g0 + j);
            }
            float r = 1.f/(1.f + expf(-(xr + ra[i] + bhh_s[     j])));
            float z = 1.f/(1.f + expf(-(xz + za[i] + bhh_s[32 + j])));
            float n = tanhf(xn + r*(na[i] + bhh_s[64 + j]));
            float hp = hs[(wq*4 + i)*256 + g0 + j];
            float hv = (1.f - z)*n + z*hp;
            __stcg(d_hping + (((size_t)dir*2 + (parity^1))*256 + b)*256 + g0 + j, hv);
            outbuf[((size_t)t_in*256 + b)*512 + (size_t)dir*256 + g0 + j] = hv;
        }
        __threadfence();
        grid_barrier((unsigned)(s_ + 1));
    }
}

// ---------------- xp1 GEMM: [131072 x 512] x [512 x 768] per dir, + bias ----------------
__global__ void __launch_bounds__(256) gemm_xp1_kernel(
    const float* __restrict__ wih, const float* __restrict__ bih) {
    __shared__ float As[16][132];
    __shared__ float Bs[16][132];
    const int mt  = blockIdx.x;
    const int nt  = blockIdx.y;
    const int dir = nt / 6;
    const int n0  = (nt % 6) * 128;
    const int tid = threadIdx.x;
    const int tx  = tid & 15;
    const int ty  = tid >> 4;
    const float* A  = d_h1;
    const float* Bm = wih + (size_t)dir * 768 * 512;

    float c[2][2][4][4];
    #pragma unroll
    for (int a = 0; a < 2; a++)
    #pragma unroll
    for (int bq = 0; bq < 2; bq++)
    #pragma unroll
    for (int i = 0; i < 4; i++)
    #pragma unroll
    for (int jn = 0; jn < 4; jn++) c[a][bq][i][jn] = 0.f;

    for (int k0 = 0; k0 < 512; k0 += 16) {
        #pragma unroll
        for (int l = 0; l < 2; l++) {
            int fid = tid + l*256;
            int m   = fid >> 2;
            int kq  = (fid & 3) << 2;
            float4 va = *(const float4*)(A  + ((size_t)mt*128 + m)*512 + k0 + kq);
            As[kq+0][m] = va.x; As[kq+1][m] = va.y; As[kq+2][m] = va.z; As[kq+3][m] = va.w;
            float4 vb = *(const float4*)(Bm + ((size_t)(n0 + m))*512 + k0 + kq);
            Bs[kq+0][m] = vb.x; Bs[kq+1][m] = vb.y; Bs[kq+2][m] = vb.z; Bs[kq+3][m] = vb.w;
        }
        __syncthreads();
        #pragma unroll
        for (int k = 0; k < 16; k++) {
            float4 a0  = *(const float4*)&As[k][ty*4];
            float4 a1  = *(const float4*)&As[k][64 + ty*4];
            float4 bb0 = *(const float4*)&Bs[k][tx*4];
            float4 bb1 = *(const float4*)&Bs[k][64 + tx*4];
            float av[2][4] = {{a0.x,a0.y,a0.z,a0.w},{a1.x,a1.y,a1.z,a1.w}};
            float bv[2][4] = {{bb0.x,bb0.y,bb0.z,bb0.w},{bb1.x,bb1.y,bb1.z,bb1.w}};
            #pragma unroll
            for (int mh = 0; mh < 2; mh++)
            #pragma unroll
            for (int i = 0; i < 4; i++)
            #pragma unroll
            for (int nh = 0; nh < 2; nh++)
            #pragma unroll
            for (int jn = 0; jn < 4; jn++)
                c[mh][nh][i][jn] += av[mh][i] * bv[nh][jn];
        }
        __syncthreads();
    }

    #pragma unroll
    for (int mh = 0; mh < 2; mh++)
    #pragma unroll
    for (int i = 0; i < 4; i++) {
        size_t m = (size_t)mt*128 + mh*64 + ty*4 + i;
        float* orow = d_xp1 + ((size_t)dir*131072 + m)*768;
        #pragma unroll
        for (int nh = 0; nh < 2; nh++) {
            int nb_ = n0 + nh*64 + tx*4;
            float4 bias = *(const float4*)(bih + dir*768 + nb_);
            float4 v;
            v.x = c[mh][nh][i][0] + bias.x;
            v.y = c[mh][nh][i][1] + bias.y;
            v.z = c[mh][nh][i][2] + bias.z;
            v.w = c[mh][nh][i][3] + bias.w;
            *(float4*)(orow + nb_) = v;
        }
    }
}

// ---------------- W1 transpose: [128][262144] -> [262144][128] ----------------
__global__ void __launch_bounds__(256) transpose_w1_kernel(const float* __restrict__ W1) {
    __shared__ float tile[32][33];
    const int c0 = blockIdx.x * 32;
    const int o0 = blockIdx.y * 32;
    const int c = threadIdx.x & 31;
    const int r = threadIdx.x >> 5;
    #pragma unroll
    for (int p = 0; p < 4; p++) {
        int rr = r + p*8;
        tile[rr][c] = W1[(size_t)(o0+rr)*262144 + c0 + c];
    }
    __syncthreads();
    #pragma unroll
    for (int p = 0; p < 4; p++) {
        int rr = r + p*8;
        d_W1t[(size_t)(c0+rr)*128 + o0 + c] = tile[c][rr];
    }
}

// ---------------- FC partials: fc1p[t][b][o] = sum_j h2[t][b][j]*W1t[t*512+j][o] ----------------
__global__ void __launch_bounds__(256) fc_part_kernel() {
    extern __shared__ float hsm[]; // [32][512]
    const int t   = blockIdx.x;
    const int tid = threadIdx.x;
    const int og  = tid & 31;      // 4 o's each
    const int bq  = tid >> 5;      // 4 b's each
    for (int bg = 0; bg < 8; bg++) {
        __syncthreads();
        #pragma unroll
        for (int q = 0; q < 16; q++) {
            int fid = tid + q*256;
            int lb = fid >> 7;
            int kq = (fid & 127) << 2;
            *(float4*)&hsm[lb*512 + kq] =
                *(const float4*)(d_h2 + ((size_t)t*256 + bg*32 + lb)*512 + kq);
        }
        __syncthreads();
        float acc[4][4];
        #pragma unroll
        for (int a = 0; a < 4; a++)
        #pragma unroll
        for (int b = 0; b < 4; b++) acc[a][b] = 0.f;
        const float* wbase = d_W1t + (size_t)t*512*128 + og*4;
        for (int j4 = 0; j4 < 128; j4++) {
            float4 w0 = __ldg((const float4*)(wbase + (size_t)(j4*4+0)*128));
            float4 w1 = __ldg((const float4*)(wbase + (size_t)(j4*4+1)*128));
            float4 w2 = __ldg((const float4*)(wbase + (size_t)(j4*4+2)*128));
            float4 w3 = __ldg((const float4*)(wbase + (size_t)(j4*4+3)*128));
            #pragma unroll
            for (int bb = 0; bb < 4; bb++) {
                float4 hv = *(const float4*)&hsm[(bq*4+bb)*512 + j4*4];
                acc[0][bb] += hv.x*w0.x + hv.y*w1.x + hv.z*w2.x + hv.w*w3.x;
                acc[1][bb] += hv.x*w0.y + hv.y*w1.y + hv.z*w2.y + hv.w*w3.y;
                acc[2][bb] += hv.x*w0.z + hv.y*w1.z + hv.z*w2.z + hv.w*w3.z;
                acc[3][bb] += hv.x*w0.w + hv.y*w1.w + hv.z*w2.w + hv.w*w3.w;
            }
        }
        #pragma unroll
        for (int bb = 0; bb < 4; bb++) {
            float4 v = make_float4(acc[0][bb], acc[1][bb], acc[2][bb], acc[3][bb]);
            *(float4*)(d_fc1p + ((size_t)t*256 + bg*32 + bq*4 + bb)*128 + og*4) = v;
        }
    }
}

// ---------------- final reduce + MLP head ----------------
__global__ void __launch_bounds__(128) fc_reduce_kernel(
    const float* __restrict__ b1, const float* __restrict__ W2,
    const float* __restrict__ b2, float* __restrict__ out) {
    const int b = blockIdx.x;
    const int o = threadIdx.x;
    float s = b1[o];
    for (int t = 0; t < 512; t++)
        s += d_fc1p[((size_t)t*256 + b)*128 + o];
    float v = s > 0.f ? s : 0.01f*s;
    float c = v * __ldg(W2 + o);
    __shared__ float red[128];
    red[o] = c;
    __syncthreads();
    for (int st = 64; st > 0; st >>= 1) {
        if (o < st) red[o] += red[o + st];
        __syncthreads();
    }
    if (o == 0) out[b] = 1.f/(1.f + expf(-(red[0] + b2[0])));
}

// ---------------- launch ----------------
extern "C" void kernel_launch(void* const* d_in, const int* in_sizes, int n_in,
                              void* d_out, int out_size) {
    const int*   inputs = (const int*)  d_in[0];
    const float* emb    = (const float*)d_in[1];
    const float* wih0   = (const float*)d_in[2];
    const float* whh0   = (const float*)d_in[3];
    const float* bih0   = (const float*)d_in[4];
    const float* bhh0   = (const float*)d_in[5];
    const float* wih1   = (const float*)d_in[6];
    const float* whh1   = (const float*)d_in[7];
    const float* bih1   = (const float*)d_in[8];
    const float* bhh1   = (const float*)d_in[9];
    const float* W1     = (const float*)d_in[10];
    const float* b1     = (const float*)d_in[11];
    const float* W2     = (const float*)d_in[12];
    const float* b2     = (const float*)d_in[13];
    float* out = (float*)d_out;

    cudaFuncSetAttribute((const void*)rec_kernel<0>,
                         cudaFuncAttributeMaxDynamicSharedMemorySize, REC_SMEM);
    cudaFuncSetAttribute((const void*)rec_kernel<1>,
                         cudaFuncAttributeMaxDynamicSharedMemorySize, REC_SMEM);
    cudaFuncSetAttribute((const void*)fc_part_kernel,
                         cudaFuncAttributeMaxDynamicSharedMemorySize, 65536);

    proj0_kernel<<<130, 256>>>(emb, wih0, bih0);
    transpose_w1_kernel<<<dim3(8192, 4), 256>>>(W1);
    reset_bar_kernel<<<1, 1>>>();
    rec_kernel<0><<<128, 256, REC_SMEM>>>(inputs, whh0, bhh0);
    gemm_xp1_kernel<<<dim3(1024, 12), 256>>>(wih1, bih1);
    reset_bar_kernel<<<1, 1>>>();
    rec_kernel<1><<<128, 256, REC_SMEM>>>(inputs, whh1, bhh1);
    fc_part_kernel<<<512, 256, 65536>>>();
    fc_reduce_kernel<<<256, 128>>>(b1, W2, b2, out);
}

// round 7
// speedup vs baseline: 1.4805x; 1.4805x over previous
#include <cuda_runtime.h>
#include <cuda_bf16.h>
#include <math.h>
#include <stddef.h>
#include <stdint.h>

// B=256, T=512, V=64(65 rows), E=128, H=256, 3H=768, D=2

// ---------------- PTX helpers (baseline ISA only: sm_80-era, safe on sm_103) ----------------
__device__ __forceinline__ uint32_t smem_to_u32(const void* p) {
    uint32_t a;
    asm("{ .reg .u64 t; cvta.to.shared.u64 t, %1; cvt.u32.u64 %0, t; }" : "=r"(a) : "l"(p));
    return a;
}
__device__ __forceinline__ void cp16(uint32_t s, const void* g) {
    asm volatile("cp.async.cg.shared.global [%0], [%1], 16;" :: "r"(s), "l"(g) : "memory");
}
#define CP_COMMIT() asm volatile("cp.async.commit_group;" ::: "memory")
#define CP_WAIT(n)  asm volatile("cp.async.wait_group %0;" :: "n"(n) : "memory")
#define LDSM_X4(r0, r1, r2, r3, addr) \
    asm volatile("ldmatrix.sync.aligned.m8n8.x4.shared.b16 {%0,%1,%2,%3}, [%4];" \
        : "=r"(r0), "=r"(r1), "=r"(r2), "=r"(r3) : "r"(addr))

__device__ __forceinline__ void mma16816(float* c, const uint32_t* a, const uint32_t* b) {
    asm volatile(
        "mma.sync.aligned.m16n8k16.row.col.f32.bf16.bf16.f32 "
        "{%0,%1,%2,%3}, {%4,%5,%6,%7}, {%8,%9}, {%0,%1,%2,%3};"
        : "+f"(c[0]), "+f"(c[1]), "+f"(c[2]), "+f"(c[3])
        : "r"(a[0]), "r"(a[1]), "r"(a[2]), "r"(a[3]), "r"(b[0]), "r"(b[1]));
}

#define SWZ128(b) ((b) ^ (((b) >> 3) & 0x70))

// ---------------- static scratch ----------------
__device__ float d_ptab [2*65*768];
__device__ float d_hping[2*2*256*256];
__device__ float d_h1   [512*256*512];
__device__ float d_xp1  [2*512*256*768];
__device__ float d_h2   [512*256*512];
__device__ float d_fc1p [512*256*128];
__device__ __nv_bfloat16 d_h1hi[67108864], d_h1lo[67108864];
__device__ __nv_bfloat16 d_h2hi[67108864], d_h2lo[67108864];
__device__ __nv_bfloat16 d_wihhi[786432], d_wihlo[786432];
__device__ __nv_bfloat16 d_W1hi[33554432], d_W1lo[33554432];
__device__ unsigned d_bar_cnt[512];
__device__ unsigned d_bar_phase[512];

__global__ void reset_bar_kernel() {
    d_bar_cnt[threadIdx.x] = 0u;
    d_bar_phase[threadIdx.x] = 0u;
}

// ---------------- group barrier: 8 CTAs per (dir, batch-slice) ----------------
__device__ __forceinline__ void group_barrier(int gid, unsigned target) {
    __syncthreads();
    if (threadIdx.x == 0) {
        __threadfence();
        unsigned old = atomicAdd(&d_bar_cnt[gid*32], 1u);
        if (old == target*8u - 1u) {
            atomicExch(&d_bar_phase[gid*32], target);
        } else {
            while (*((volatile unsigned*)&d_bar_phase[gid*32]) < target) { __nanosleep(32); }
            __threadfence();
        }
    }
    __syncthreads();
}

// ---------------- L0 proj table ----------------
__global__ void __launch_bounds__(256) proj0_kernel(const float* __restrict__ emb,
                                                    const float* __restrict__ wih,
                                                    const float* __restrict__ bih) {
    const int d = blockIdx.x / 65;
    const int v = blockIdx.x % 65;
    __shared__ float es[128];
    if (threadIdx.x < 128) es[threadIdx.x] = emb[v*128 + threadIdx.x];
    __syncthreads();
    for (int g = threadIdx.x; g < 768; g += 256) {
        const float* w = wih + ((size_t)d*768 + g)*128;
        float s = bih[d*768 + g];
        #pragma unroll 4
        for (int e = 0; e < 128; e++) s += es[e]*__ldg(w + e);
        d_ptab[((size_t)d*65 + v)*768 + g] = s;
    }
}

// ---------------- fp32 -> bf16 hi/lo split ----------------
__global__ void __launch_bounds__(256) split_kernel(const float* __restrict__ x,
        __nv_bfloat16* __restrict__ hi, __nv_bfloat16* __restrict__ lo, size_t n4) {
    size_t i = (size_t)blockIdx.x*256 + threadIdx.x;
    size_t stride = (size_t)gridDim.x*256;
    for (; i < n4; i += stride) {
        float4 v = __ldg((const float4*)x + i);
        __nv_bfloat16 a0 = __float2bfloat16(v.x), a1 = __float2bfloat16(v.y);
        __nv_bfloat16 a2 = __float2bfloat16(v.z), a3 = __float2bfloat16(v.w);
        __nv_bfloat16 l0 = __float2bfloat16(v.x - __bfloat162float(a0));
        __nv_bfloat16 l1 = __float2bfloat16(v.y - __bfloat162float(a1));
        __nv_bfloat16 l2 = __float2bfloat16(v.z - __bfloat162float(a2));
        __nv_bfloat16 l3 = __float2bfloat16(v.w - __bfloat162float(a3));
        ((__nv_bfloat162*)hi)[2*i]   = __halves2bfloat162(a0, a1);
        ((__nv_bfloat162*)hi)[2*i+1] = __halves2bfloat162(a2, a3);
        ((__nv_bfloat162*)lo)[2*i]   = __halves2bfloat162(l0, l1);
        ((__nv_bfloat162*)lo)[2*i+1] = __halves2bfloat162(l2, l3);
    }
}

// ---------------- recurrence (both layers) ----------------
// 128 CTAs = dir(2) x batch-slice(8 x 32b) x gate-slice(8 x 32 units)
#define WS_STRIDE 772
#define REC_SMEM ((32*WS_STRIDE + 32*256)*4)

template<int LAYER>
__global__ void __launch_bounds__(256, 1) rec_kernel(
    const int* __restrict__ inputs,
    const float* __restrict__ w_hh,
    const float* __restrict__ b_hh) {
    extern __shared__ float smem[];
    float* ws = smem;                  // [32 j][WS_STRIDE]
    float* hs = smem + 32*WS_STRIDE;   // [32 b][256 k]
    __shared__ float bhh_s[96];

    const int bid = blockIdx.x;
    const int dir = bid >> 6;
    const int rem = bid & 63;
    const int b0  = (rem >> 3) * 32;
    const int g0  = (rem & 7) * 32;
    const int gid = bid >> 3;
    const int tid = threadIdx.x;
    const int wq  = tid >> 5;
    const int j   = tid & 31;

    for (int row = wq; row < 96; row += 8) {
        const int g  = row >> 5;
        const int jr = row & 31;
        const float* src = w_hh + ((size_t)dir*768 + g*256 + g0 + jr)*256;
        for (int k = j; k < 256; k += 32)
            ws[jr*WS_STRIDE + g*256 + k] = src[k];
    }
    if (tid < 96) bhh_s[tid] = b_hh[dir*768 + (tid>>5)*256 + g0 + (tid&31)];
    __syncthreads();

    const float* wj = ws + j*WS_STRIDE;

    for (int s_ = 0; s_ < 512; s_++) {
        const int parity = s_ & 1;
        if (s_ == 0) {
            #pragma unroll
            for (int q = 0; q < 8; q++)
                *(float4*)&hs[(tid + q*256)*4] = make_float4(0.f,0.f,0.f,0.f);
        } else {
            const float4* src = (const float4*)(d_hping + (((size_t)dir*2 + parity)*256 + b0)*256);
            #pragma unroll
            for (int q = 0; q < 8; q++) {
                int fid = tid + q*256;
                float4 v = __ldcg(src + fid);
                *(float4*)&hs[fid*4] = v;
            }
        }
        __syncthreads();

        const int t_in = (dir == 0) ? s_ : (511 - s_);
        float xr[4], xz[4], xn[4];
        #pragma unroll
        for (int i = 0; i < 4; i++) {
            const int b = b0 + wq*4 + i;
            if (LAYER == 0) {
                const int tok = __ldg(inputs + b*512 + t_in);
                const float* pt = d_ptab + ((size_t)dir*65 + tok)*768;
                xr[i] = __ldg(pt +       g0 + j);
                xz[i] = __ldg(pt + 256 + g0 + j);
                xn[i] = __ldg(pt + 512 + g0 + j);
            } else {
                const float* xp = d_xp1 + ((size_t)dir*131072 + (size_t)t_in*256 + b)*768;
                xr[i] = __ldg(xp +       g0 + j);
                xz[i] = __ldg(xp + 256 + g0 + j);
                xn[i] = __ldg(xp + 512 + g0 + j);
            }
        }

        float ra[4] = {0,0,0,0}, za[4] = {0,0,0,0}, na[4] = {0,0,0,0};
        #pragma unroll 8
        for (int k = 0; k < 256; k += 4) {
            float4 wr = *(const float4*)(wj + k);
            float4 wz = *(const float4*)(wj + 256 + k);
            float4 wn = *(const float4*)(wj + 512 + k);
            #pragma unroll
            for (int i = 0; i < 4; i++) {
                float4 hv = *(const float4*)(hs + (wq*4 + i)*256 + k);
                ra[i] += hv.x*wr.x; ra[i] += hv.y*wr.y; ra[i] += hv.z*wr.z; ra[i] += hv.w*wr.w;
                za[i] += hv.x*wz.x; za[i] += hv.y*wz.y; za[i] += hv.z*wz.z; za[i] += hv.w*wz.w;
                na[i] += hv.x*wn.x; na[i] += hv.y*wn.y; na[i] += hv.z*wn.z; na[i] += hv.w*wn.w;
            }
        }

        float* outbuf = (LAYER == 0) ? d_h1 : d_h2;
        #pragma unroll
        for (int i = 0; i < 4; i++) {
            const int b = b0 + wq*4 + i;
            float r = 1.f/(1.f + expf(-(xr[i] + ra[i] + bhh_s[     j])));
            float z = 1.f/(1.f + expf(-(xz[i] + za[i] + bhh_s[32 + j])));
            float n = tanhf(xn[i] + r*(na[i] + bhh_s[64 + j]));
            float hp = hs[(wq*4 + i)*256 + g0 + j];
            float hv = (1.f - z)*n + z*hp;
            __stcg(d_hping + (((size_t)dir*2 + (parity^1))*256 + b)*256 + g0 + j, hv);
            outbuf[((size_t)t_in*256 + b)*512 + (size_t)dir*256 + g0 + j] = hv;
        }
        if (s_ != 511) group_barrier(gid, (unsigned)(s_ + 1));
    }
}

// ---------------- split-bf16 warp-MMA GEMM (mma.sync m16n8k16 bf16) ----------------
// C = Ahi*Bhi^T + Ahi*Blo^T + Alo*Bhi^T (fp32 accum), A,B both K-major (row.col).
// Block tile 128x128, K-chunk 64, double-buffered cp.async, 8 warps (2m x 4n).
// MODE 0: xp1 = h1 @ wih1^T + bias.  grid (1024 mtiles, 6 ntiles, 2 dirs)
// MODE 1: fc1 partials per t.        grid (2 mtiles, 1, 512 t)
#define MMA_DSMEM (2*65536 + 1024)

template<int MODE>
__global__ void __launch_bounds__(256) mma_gemm_kernel(
    const __nv_bfloat16* __restrict__ Ah, const __nv_bfloat16* __restrict__ Al,
    const __nv_bfloat16* __restrict__ Bh, const __nv_bfloat16* __restrict__ Bl,
    const float* __restrict__ bias, float* __restrict__ outp) {
    extern __shared__ char dsm_raw[];
    const uint32_t raw  = smem_to_u32(dsm_raw);
    const uint32_t base = (raw + 1023u) & ~1023u;

    const int tid  = threadIdx.x;
    const int lane = tid & 31;
    const int wid  = tid >> 5;
    const int wm   = wid >> 2;   // 0..1  (m offset 64)
    const int wn   = wid & 3;    // 0..3  (n offset 32)

    size_t arow0, brow0, bstride, bk0;
    if (MODE == 0) {
        arow0 = (size_t)blockIdx.x * 128;
        brow0 = (size_t)blockIdx.z * 768 + (size_t)blockIdx.y * 128;
        bstride = 512; bk0 = 0;
    } else {
        arow0 = (size_t)blockIdx.z * 256 + (size_t)blockIdx.x * 128;
        brow0 = 0;
        bstride = 262144; bk0 = (size_t)blockIdx.z * 512;
    }

    float c[4][4][4];
    #pragma unroll
    for (int fm = 0; fm < 4; fm++)
    #pragma unroll
    for (int fn = 0; fn < 4; fn++)
    #pragma unroll
    for (int q = 0; q < 4; q++) c[fm][fn][q] = 0.f;

    auto issue = [&](int kc, int buf) {
        const uint32_t sb = base + (uint32_t)buf*65536u;
        #pragma unroll
        for (int v = 0; v < 4; v++) {
            int vv = tid + v*256;
            int r = vv >> 3, seg = vv & 7;
            uint32_t sw = SWZ128((uint32_t)(r*128 + seg*16));
            size_t k  = (size_t)kc*64 + (size_t)seg*8;
            size_t ga = (arow0 + r)*512 + k;
            size_t gb = (brow0 + r)*bstride + bk0 + k;
            cp16(sb +          sw, Ah + ga);
            cp16(sb + 16384u + sw, Al + ga);
            cp16(sb + 32768u + sw, Bh + gb);
            cp16(sb + 49152u + sw, Bl + gb);
        }
    };

    issue(0, 0); CP_COMMIT();

    for (int kc = 0; kc < 8; kc++) {
        if (kc < 7) {
            issue(kc + 1, (kc + 1) & 1); CP_COMMIT();
            CP_WAIT(1);
        } else {
            CP_WAIT(0);
        }
        __syncthreads();

        const uint32_t sb = base + (uint32_t)(kc & 1)*65536u;
        const int lrow = lane & 15, kseg = lane >> 4;
        const int g = lane >> 3, lr = lane & 7;
        const int nrow = ((g >> 1) & 1)*8 + lr;
        const int ks2 = g & 1;

        #pragma unroll
        for (int ki = 0; ki < 4; ki++) {
            uint32_t ahf[4][4], alf[4][4];
            #pragma unroll
            for (int fm = 0; fm < 4; fm++) {
                uint32_t off = SWZ128((uint32_t)((wm*64 + fm*16 + lrow)*128 + ki*32 + kseg*16));
                LDSM_X4(ahf[fm][0], ahf[fm][1], ahf[fm][2], ahf[fm][3], sb + off);
                LDSM_X4(alf[fm][0], alf[fm][1], alf[fm][2], alf[fm][3], sb + 16384u + off);
            }
            uint32_t bhf[4][2], blf[4][2];
            #pragma unroll
            for (int fp = 0; fp < 2; fp++) {
                uint32_t off = SWZ128((uint32_t)((wn*32 + fp*16 + nrow)*128 + ki*32 + ks2*16));
                LDSM_X4(bhf[fp*2][0], bhf[fp*2][1], bhf[fp*2+1][0], bhf[fp*2+1][1], sb + 32768u + off);
                LDSM_X4(blf[fp*2][0], blf[fp*2][1], blf[fp*2+1][0], blf[fp*2+1][1], sb + 49152u + off);
            }
            #pragma unroll
            for (int fm = 0; fm < 4; fm++)
            #pragma unroll
            for (int fn = 0; fn < 4; fn++) {
                mma16816(c[fm][fn], ahf[fm], bhf[fn]);
                mma16816(c[fm][fn], ahf[fm], blf[fn]);
                mma16816(c[fm][fn], alf[fm], bhf[fn]);
            }
        }
        __syncthreads();
    }

    // epilogue
    const int l4 = lane >> 2;
    const int l2 = (lane & 3)*2;
    #pragma unroll
    for (int fm = 0; fm < 4; fm++) {
        const int mr0 = wm*64 + fm*16 + l4;
        #pragma unroll
        for (int fn = 0; fn < 4; fn++) {
            const int col = wn*32 + fn*8 + l2;
            if (MODE == 0) {
                const int gcol = blockIdx.y*128 + col;
                float2 bv = *(const float2*)(bias + blockIdx.z*768 + gcol);
                size_t m0 = (size_t)blockIdx.z*131072 + (size_t)blockIdx.x*128 + mr0;
                float2 v0 = make_float2(c[fm][fn][0] + bv.x, c[fm][fn][1] + bv.y);
                float2 v1 = make_float2(c[fm][fn][2] + bv.x, c[fm][fn][3] + bv.y);
                *(float2*)(outp + m0*768 + gcol)        = v0;
                *(float2*)(outp + (m0 + 8)*768 + gcol)  = v1;
            } else {
                size_t m0 = (size_t)blockIdx.z*256 + (size_t)blockIdx.x*128 + mr0;
                *(float2*)(outp + m0*128 + col)       = make_float2(c[fm][fn][0], c[fm][fn][1]);
                *(float2*)(outp + (m0 + 8)*128 + col) = make_float2(c[fm][fn][2], c[fm][fn][3]);
            }
        }
    }
}

// ---------------- final reduce + MLP head ----------------
__global__ void __launch_bounds__(128) fc_reduce_kernel(
    const float* __restrict__ b1, const float* __restrict__ W2,
    const float* __restrict__ b2, float* __restrict__ out) {
    const int b = blockIdx.x;
    const int o = threadIdx.x;
    float s = b1[o];
    for (int t = 0; t < 512; t++)
        s += d_fc1p[((size_t)t*256 + b)*128 + o];
    float v = s > 0.f ? s : 0.01f*s;
    float c = v * __ldg(W2 + o);
    __shared__ float red[128];
    red[o] = c;
    __syncthreads();
    for (int st = 64; st > 0; st >>= 1) {
        if (o < st) red[o] += red[o + st];
        __syncthreads();
    }
    if (o == 0) out[b] = 1.f/(1.f + expf(-(red[0] + b2[0])));
}

// ---------------- launch ----------------
extern "C" void kernel_launch(void* const* d_in, const int* in_sizes, int n_in,
                              void* d_out, int out_size) {
    const int*   inputs = (const int*)  d_in[0];
    const float* emb    = (const float*)d_in[1];
    const float* wih0   = (const float*)d_in[2];
    const float* whh0   = (const float*)d_in[3];
    const float* bih0   = (const float*)d_in[4];
    const float* bhh0   = (const float*)d_in[5];
    const float* wih1   = (const float*)d_in[6];
    const float* whh1   = (const float*)d_in[7];
    const float* bih1   = (const float*)d_in[8];
    const float* bhh1   = (const float*)d_in[9];
    const float* W1     = (const float*)d_in[10];
    const float* b1     = (const float*)d_in[11];
    const float* W2     = (const float*)d_in[12];
    const float* b2     = (const float*)d_in[13];
    float* out = (float*)d_out;

    cudaFuncSetAttribute((const void*)rec_kernel<0>,
                         cudaFuncAttributeMaxDynamicSharedMemorySize, REC_SMEM);
    cudaFuncSetAttribute((const void*)rec_kernel<1>,
                         cudaFuncAttributeMaxDynamicSharedMemorySize, REC_SMEM);
    cudaFuncSetAttribute((const void*)mma_gemm_kernel<0>,
                         cudaFuncAttributeMaxDynamicSharedMemorySize, MMA_DSMEM);
    cudaFuncSetAttribute((const void*)mma_gemm_kernel<1>,
                         cudaFuncAttributeMaxDynamicSharedMemorySize, MMA_DSMEM);

    __nv_bfloat16 *h1hi, *h1lo, *h2hi, *h2lo, *wihhi, *wihlo, *W1hi, *W1lo;
    cudaGetSymbolAddress((void**)&h1hi, d_h1hi);
    cudaGetSymbolAddress((void**)&h1lo, d_h1lo);
    cudaGetSymbolAddress((void**)&h2hi, d_h2hi);
    cudaGetSymbolAddress((void**)&h2lo, d_h2lo);
    cudaGetSymbolAddress((void**)&wihhi, d_wihhi);
    cudaGetSymbolAddress((void**)&wihlo, d_wihlo);
    cudaGetSymbolAddress((void**)&W1hi, d_W1hi);
    cudaGetSymbolAddress((void**)&W1lo, d_W1lo);
    float *h1p, *h2p, *xp1p, *fc1p;
    cudaGetSymbolAddress((void**)&h1p, d_h1);
    cudaGetSymbolAddress((void**)&h2p, d_h2);
    cudaGetSymbolAddress((void**)&xp1p, d_xp1);
    cudaGetSymbolAddress((void**)&fc1p, d_fc1p);

    proj0_kernel<<<130, 256>>>(emb, wih0, bih0);
    split_kernel<<<768, 256>>>(wih1, wihhi, wihlo, 196608);
    split_kernel<<<4096, 256>>>(W1, W1hi, W1lo, 8388608);
    reset_bar_kernel<<<1, 512>>>();
    rec_kernel<0><<<128, 256, REC_SMEM>>>(inputs, whh0, bhh0);
    split_kernel<<<4096, 256>>>(h1p, h1hi, h1lo, 16777216);
    mma_gemm_kernel<0><<<dim3(1024, 6, 2), 256, MMA_DSMEM>>>(h1hi, h1lo, wihhi, wihlo, bih1, xp1p);
    reset_bar_kernel<<<1, 512>>>();
    rec_kernel<1><<<128, 256, REC_SMEM>>>(inputs, whh1, bhh1);
    split_kernel<<<4096, 256>>>(h2p, h2hi, h2lo, 16777216);
    mma_gemm_kernel<1><<<dim3(2, 1, 512), 256, MMA_DSMEM>>>(h2hi, h2lo, W1hi, W1lo, nullptr, fc1p);
    fc_reduce_kernel<<<256, 128>>>(b1, W2, b2, out);
}

// round 8
// speedup vs baseline: 1.9848x; 1.3407x over previous
#include <cuda_runtime.h>
#include <cuda_bf16.h>
#include <math.h>
#include <stddef.h>
#include <stdint.h>

// B=256, T=512, V=64(65 rows), E=128, H=256, 3H=768, D=2

// ---------------- PTX helpers (baseline ISA only: sm_80-era, safe on sm_103) ----------------
__device__ __forceinline__ uint32_t smem_to_u32(const void* p) {
    uint32_t a;
    asm("{ .reg .u64 t; cvta.to.shared.u64 t, %1; cvt.u32.u64 %0, t; }" : "=r"(a) : "l"(p));
    return a;
}
__device__ __forceinline__ void cp16(uint32_t s, const void* g) {
    asm volatile("cp.async.cg.shared.global [%0], [%1], 16;" :: "r"(s), "l"(g) : "memory");
}
#define CP_COMMIT() asm volatile("cp.async.commit_group;" ::: "memory")
#define CP_WAIT(n)  asm volatile("cp.async.wait_group %0;" :: "n"(n) : "memory")
#define LDSM_X4(r0, r1, r2, r3, addr) \
    asm volatile("ldmatrix.sync.aligned.m8n8.x4.shared.b16 {%0,%1,%2,%3}, [%4];" \
        : "=r"(r0), "=r"(r1), "=r"(r2), "=r"(r3) : "r"(addr))
#define LDSM_X2(r0, r1, addr) \
    asm volatile("ldmatrix.sync.aligned.m8n8.x2.shared.b16 {%0,%1}, [%2];" \
        : "=r"(r0), "=r"(r1) : "r"(addr))

__device__ __forceinline__ void mma16816(float* c, const uint32_t* a, const uint32_t* b) {
    asm volatile(
        "mma.sync.aligned.m16n8k16.row.col.f32.bf16.bf16.f32 "
        "{%0,%1,%2,%3}, {%4,%5,%6,%7}, {%8,%9}, {%0,%1,%2,%3};"
        : "+f"(c[0]), "+f"(c[1]), "+f"(c[2]), "+f"(c[3])
        : "r"(a[0]), "r"(a[1]), "r"(a[2]), "r"(a[3]), "r"(b[0]), "r"(b[1]));
}

#define SWZ128(b) ((b) ^ (((b) >> 3) & 0x70))

// pack 4 floats -> hi/lo bf16 pairs (8 bytes each)
__device__ __forceinline__ void split4(float4 v, uint2& hi, uint2& lo) {
    __nv_bfloat16 a0 = __float2bfloat16(v.x), a1 = __float2bfloat16(v.y);
    __nv_bfloat16 a2 = __float2bfloat16(v.z), a3 = __float2bfloat16(v.w);
    __nv_bfloat16 l0 = __float2bfloat16(v.x - __bfloat162float(a0));
    __nv_bfloat16 l1 = __float2bfloat16(v.y - __bfloat162float(a1));
    __nv_bfloat16 l2 = __float2bfloat16(v.z - __bfloat162float(a2));
    __nv_bfloat16 l3 = __float2bfloat16(v.w - __bfloat162float(a3));
    __nv_bfloat162 h01 = __halves2bfloat162(a0, a1), h23 = __halves2bfloat162(a2, a3);
    __nv_bfloat162 m01 = __halves2bfloat162(l0, l1), m23 = __halves2bfloat162(l2, l3);
    hi.x = *(uint32_t*)&h01; hi.y = *(uint32_t*)&h23;
    lo.x = *(uint32_t*)&m01; lo.y = *(uint32_t*)&m23;
}

// ---------------- static scratch ----------------
__device__ float d_ptab [2*65*768];
__device__ float d_hping[2*2*256*256];
__device__ float d_h1   [512*256*512];
__device__ float d_xp1  [2*512*256*768];
__device__ float d_h2   [512*256*512];
__device__ float d_fc1p [512*256*128];
__device__ __nv_bfloat16 d_h1hi[67108864], d_h1lo[67108864];
__device__ __nv_bfloat16 d_h2hi[67108864], d_h2lo[67108864];
__device__ __nv_bfloat16 d_wihhi[786432], d_wihlo[786432];
__device__ __nv_bfloat16 d_W1hi[33554432], d_W1lo[33554432];
__device__ unsigned d_bar_cnt[512];
__device__ unsigned d_bar_phase[512];

__global__ void reset_bar_kernel() {
    d_bar_cnt[threadIdx.x] = 0u;
    d_bar_phase[threadIdx.x] = 0u;
}

// ---------------- group barrier: 8 CTAs per (dir, batch-slice) ----------------
__device__ __forceinline__ void group_barrier(int gid, unsigned target) {
    __syncthreads();
    if (threadIdx.x == 0) {
        __threadfence();
        unsigned old = atomicAdd(&d_bar_cnt[gid*32], 1u);
        if (old == target*8u - 1u) {
            atomicExch(&d_bar_phase[gid*32], target);
        } else {
            while (*((volatile unsigned*)&d_bar_phase[gid*32]) < target) { __nanosleep(32); }
            __threadfence();
        }
    }
    __syncthreads();
}

// ---------------- L0 proj table ----------------
__global__ void __launch_bounds__(256) proj0_kernel(const float* __restrict__ emb,
                                                    const float* __restrict__ wih,
                                                    const float* __restrict__ bih) {
    const int d = blockIdx.x / 65;
    const int v = blockIdx.x % 65;
    __shared__ float es[128];
    if (threadIdx.x < 128) es[threadIdx.x] = emb[v*128 + threadIdx.x];
    __syncthreads();
    for (int g = threadIdx.x; g < 768; g += 256) {
        const float* w = wih + ((size_t)d*768 + g)*128;
        float s = bih[d*768 + g];
        #pragma unroll 4
        for (int e = 0; e < 128; e++) s += es[e]*__ldg(w + e);
        d_ptab[((size_t)d*65 + v)*768 + g] = s;
    }
}

// ---------------- fp32 -> bf16 hi/lo split (global) ----------------
__global__ void __launch_bounds__(256) split_kernel(const float* __restrict__ x,
        __nv_bfloat16* __restrict__ hi, __nv_bfloat16* __restrict__ lo, size_t n4) {
    size_t i = (size_t)blockIdx.x*256 + threadIdx.x;
    size_t stride = (size_t)gridDim.x*256;
    for (; i < n4; i += stride) {
        float4 v = __ldg((const float4*)x + i);
        uint2 h, l;
        split4(v, h, l);
        ((uint2*)hi)[i] = h;
        ((uint2*)lo)[i] = l;
    }
}

// ---------------- MMA recurrence (both layers) ----------------
// 128 CTAs = dir(2) x batch-slice(8 x 32 rows) x unit-slice(8 x 32 units)
// Per step: G[32 x 96] = h[32 x 256] @ Wslice[96 x 256]^T via split-bf16 3-pass mma.
// SMEM layout (1024-aligned base):
//   WHI  @ 0      : 4 chunks x (96 rows x 128B)   = 49152
//   WLO  @ 49152  : 49152
//   HHI  @ 98304  : 4 chunks x (32 rows x 128B)   = 16384
//   HLO  @ 114688 : 16384
//   G    @ 131072 : 32 x 100 floats               = 12800
//   HPREV@ 143872 : 32 x 36 floats                = 4608
#define RECM_SMEM (148480 + 1024)

template<int LAYER>
__global__ void __launch_bounds__(256, 1) rec_mma_kernel(
    const int* __restrict__ inputs,
    const float* __restrict__ w_hh,
    const float* __restrict__ b_hh) {
    extern __shared__ char sm_raw[];
    __shared__ float bhh_s[96];
    const uint32_t raw  = smem_to_u32(sm_raw);
    const uint32_t base = (raw + 1023u) & ~1023u;
    char* sb = sm_raw + (base - raw);
    float* Gs    = (float*)(sb + 131072);
    float* Hprev = (float*)(sb + 143872);

    const int bid = blockIdx.x;
    const int dir = bid >> 6;
    const int rem = bid & 63;
    const int bs  = rem >> 3;
    const int us  = rem & 7;
    const int b0  = bs * 32;
    const int j0  = us * 32;
    const int gid = dir*8 + bs;
    const int tid = threadIdx.x;
    const int lane = tid & 31;
    const int wid  = tid >> 5;

    // ---- one-time: W_hh slice -> bf16 hi/lo swizzled smem (gate-interleaved rows) ----
    {
        const int k0 = (tid & 7) * 32;
        #pragma unroll
        for (int rr = 0; rr < 3; rr++) {
            const int lr = rr*32 + (tid >> 3);
            const int g  = lr >> 5;
            const float* src = w_hh + ((size_t)dir*768 + g*256 + j0 + (lr & 31))*256 + k0;
            const uint32_t cb = (uint32_t)(k0 >> 6)*12288u + (uint32_t)lr*128u + (uint32_t)(k0 & 63)*2u;
            #pragma unroll
            for (int q = 0; q < 8; q++) {
                float4 v = __ldg((const float4*)src + q);
                uint2 h, l;
                split4(v, h, l);
                uint32_t off = SWZ128(cb + q*8);
                *(uint2*)(sb + off)          = h;
                *(uint2*)(sb + 49152u + off) = l;
            }
        }
    }
    if (tid < 96) bhh_s[tid] = b_hh[dir*768 + (tid>>5)*256 + j0 + (tid & 31)];
    // zero h tiles + hprev
    for (int i = tid; i < 2048; i += 256)
        ((uint4*)(sb + 98304))[i] = make_uint4(0,0,0,0);
    for (int i = tid; i < 1152; i += 256)
        Hprev[i] = 0.f;
    __syncthreads();

    // per-thread nonlinearity mapping
    const int bb = tid >> 3;
    const int ju = (tid & 7) * 4;
    const int bg = b0 + bb;

    // MMA lane mappings
    const int wm = wid >> 2, wn = wid & 3;
    const int lrow = lane & 15, kseg = lane >> 4;
    const int g8 = lane >> 3, lr8 = lane & 7;
    const int nrx4 = ((g8 >> 1) & 1)*8 + lr8;
    const int ksx4 = g8 & 1;
    const int lx = lane & 15;
    const int rowb2 = lx & 7, kh2 = (lx >> 3) & 1;

    for (int s_ = 0; s_ < 512; s_++) {
        const int parity = s_ & 1;
        if (s_ > 0) {
            // h fp32 -> bf16 hi/lo swizzled tiles
            const int r  = tid >> 3;
            const int k0 = (tid & 7) * 32;
            const float4* src = (const float4*)(d_hping +
                (((size_t)dir*2 + parity)*256 + b0 + r)*256 + k0);
            const uint32_t cb = (uint32_t)(k0 >> 6)*4096u + (uint32_t)r*128u + (uint32_t)(k0 & 63)*2u;
            #pragma unroll
            for (int q = 0; q < 8; q++) {
                float4 v = __ldcg(src + q);
                uint2 h, l;
                split4(v, h, l);
                uint32_t off = SWZ128(cb + q*8);
                *(uint2*)(sb + 98304u  + off) = h;
                *(uint2*)(sb + 114688u + off) = l;
            }
        }

        // prefetch x-projections
        const int t_in = (dir == 0) ? s_ : (511 - s_);
        float4 xr4, xz4, xn4;
        if (LAYER == 0) {
            const int tok = __ldg(inputs + bg*512 + t_in);
            const float* pt = d_ptab + ((size_t)dir*65 + tok)*768 + j0 + ju;
            xr4 = __ldg((const float4*)(pt));
            xz4 = __ldg((const float4*)(pt + 256));
            xn4 = __ldg((const float4*)(pt + 512));
        } else {
            const float* xp = d_xp1 + ((size_t)dir*131072 + (size_t)t_in*256 + bg)*768 + j0 + ju;
            xr4 = __ldg((const float4*)(xp));
            xz4 = __ldg((const float4*)(xp + 256));
            xn4 = __ldg((const float4*)(xp + 512));
        }
        __syncthreads();

        // ---- MMA: G = h @ Wslice^T, 3-pass split ----
        float c[3][4];
        #pragma unroll
        for (int fn = 0; fn < 3; fn++)
            #pragma unroll
            for (int q = 0; q < 4; q++) c[fn][q] = 0.f;

        #pragma unroll
        for (int ks = 0; ks < 16; ks++) {
            const int ck = ks >> 2, ki = ks & 3;
            const uint32_t ain = base + 98304u + (uint32_t)ck*4096u +
                SWZ128((uint32_t)((wm*16 + lrow)*128 + ki*32 + kseg*16));
            uint32_t ah[4], al[4];
            LDSM_X4(ah[0], ah[1], ah[2], ah[3], ain);
            LDSM_X4(al[0], al[1], al[2], al[3], ain + 16384u);
            const uint32_t bcb = base + (uint32_t)ck*12288u;
            const uint32_t b4 = bcb +
                SWZ128((uint32_t)((wn*24 + nrx4)*128 + ki*32 + ksx4*16));
            const uint32_t b2 = bcb +
                SWZ128((uint32_t)((wn*24 + 16 + rowb2)*128 + ki*32 + kh2*16));
            uint32_t bh[3][2], bl[3][2];
            LDSM_X4(bh[0][0], bh[0][1], bh[1][0], bh[1][1], b4);
            LDSM_X2(bh[2][0], bh[2][1], b2);
            LDSM_X4(bl[0][0], bl[0][1], bl[1][0], bl[1][1], b4 + 49152u);
            LDSM_X2(bl[2][0], bl[2][1], b2 + 49152u);
            #pragma unroll
            for (int fn = 0; fn < 3; fn++) {
                mma16816(c[fn], ah, bh[fn]);
                mma16816(c[fn], ah, bl[fn]);
                mma16816(c[fn], al, bh[fn]);
            }
        }

        // write G to smem
        {
            const int l4 = lane >> 2, l2 = (lane & 3)*2;
            #pragma unroll
            for (int fn = 0; fn < 3; fn++) {
                const int col = wn*24 + fn*8 + l2;
                *(float2*)&Gs[(wm*16 + l4)*100 + col]     = make_float2(c[fn][0], c[fn][1]);
                *(float2*)&Gs[(wm*16 + l4 + 8)*100 + col] = make_float2(c[fn][2], c[fn][3]);
            }
        }
        __syncthreads();

        // ---- nonlinearity + h update ----
        {
            float4 gr = *(const float4*)&Gs[bb*100 + ju];
            float4 gz = *(const float4*)&Gs[bb*100 + 32 + ju];
            float4 gn = *(const float4*)&Gs[bb*100 + 64 + ju];
            float4 hp = *(const float4*)&Hprev[bb*36 + ju];
            float hn[4];
            const float* xr = &xr4.x;
            const float* xz = &xz4.x;
            const float* xn = &xn4.x;
            const float* grp = &gr.x;
            const float* gzp = &gz.x;
            const float* gnp = &gn.x;
            const float* hpp = &hp.x;
            #pragma unroll
            for (int i = 0; i < 4; i++) {
                float r = 1.f/(1.f + expf(-(xr[i] + grp[i] + bhh_s[     ju + i])));
                float z = 1.f/(1.f + expf(-(xz[i] + gzp[i] + bhh_s[32 + ju + i])));
                float n = tanhf(xn[i] + r*(gnp[i] + bhh_s[64 + ju + i]));
                hn[i] = (1.f - z)*n + z*hpp[i];
            }
            float4 hv = make_float4(hn[0], hn[1], hn[2], hn[3]);
            *(float4*)&Hprev[bb*36 + ju] = hv;
            __stcg((float4*)(d_hping + (((size_t)dir*2 + (parity^1))*256 + bg)*256 + j0 + ju), hv);
            float* outbuf = (LAYER == 0) ? d_h1 : d_h2;
            *(float4*)(outbuf + ((size_t)t_in*256 + bg)*512 + (size_t)dir*256 + j0 + ju) = hv;
        }
        if (s_ != 511) group_barrier(gid, (unsigned)(s_ + 1));
    }
}

// ---------------- split-bf16 warp-MMA GEMM (mma.sync m16n8k16 bf16) ----------------
// MODE 0: xp1 = h1 @ wih1^T + bias.  grid (1024 mtiles, 6 ntiles, 2 dirs)
// MODE 1: fc1 partials per t.        grid (2 mtiles, 1, 512 t)
#define MMA_DSMEM (2*65536 + 1024)

template<int MODE>
__global__ void __launch_bounds__(256) mma_gemm_kernel(
    const __nv_bfloat16* __restrict__ Ah, const __nv_bfloat16* __restrict__ Al,
    const __nv_bfloat16* __restrict__ Bh, const __nv_bfloat16* __restrict__ Bl,
    const float* __restrict__ bias, float* __restrict__ outp) {
    extern __shared__ char dsm_raw[];
    const uint32_t raw  = smem_to_u32(dsm_raw);
    const uint32_t base = (raw + 1023u) & ~1023u;

    const int tid  = threadIdx.x;
    const int lane = tid & 31;
    const int wid  = tid >> 5;
    const int wm   = wid >> 2;
    const int wn   = wid & 3;

    size_t arow0, brow0, bstride, bk0;
    if (MODE == 0) {
        arow0 = (size_t)blockIdx.x * 128;
        brow0 = (size_t)blockIdx.z * 768 + (size_t)blockIdx.y * 128;
        bstride = 512; bk0 = 0;
    } else {
        arow0 = (size_t)blockIdx.z * 256 + (size_t)blockIdx.x * 128;
        brow0 = 0;
        bstride = 262144; bk0 = (size_t)blockIdx.z * 512;
    }

    float c[4][4][4];
    #pragma unroll
    for (int fm = 0; fm < 4; fm++)
    #pragma unroll
    for (int fn = 0; fn < 4; fn++)
    #pragma unroll
    for (int q = 0; q < 4; q++) c[fm][fn][q] = 0.f;

    auto issue = [&](int kc, int buf) {
        const uint32_t sbb = base + (uint32_t)buf*65536u;
        #pragma unroll
        for (int v = 0; v < 4; v++) {
            int vv = tid + v*256;
            int r = vv >> 3, seg = vv & 7;
            uint32_t sw = SWZ128((uint32_t)(r*128 + seg*16));
            size_t k  = (size_t)kc*64 + (size_t)seg*8;
            size_t ga = (arow0 + r)*512 + k;
            size_t gb = (brow0 + r)*bstride + bk0 + k;
            cp16(sbb +          sw, Ah + ga);
            cp16(sbb + 16384u + sw, Al + ga);
            cp16(sbb + 32768u + sw, Bh + gb);
            cp16(sbb + 49152u + sw, Bl + gb);
        }
    };

    issue(0, 0); CP_COMMIT();

    for (int kc = 0; kc < 8; kc++) {
        if (kc < 7) {
            issue(kc + 1, (kc + 1) & 1); CP_COMMIT();
            CP_WAIT(1);
        } else {
            CP_WAIT(0);
        }
        __syncthreads();

        const uint32_t sbb = base + (uint32_t)(kc & 1)*65536u;
        const int lrow = lane & 15, kseg = lane >> 4;
        const int g = lane >> 3, lr = lane & 7;
        const int nrow = ((g >> 1) & 1)*8 + lr;
        const int ks2 = g & 1;

        #pragma unroll
        for (int ki = 0; ki < 4; ki++) {
            uint32_t ahf[4][4], alf[4][4];
            #pragma unroll
            for (int fm = 0; fm < 4; fm++) {
                uint32_t off = SWZ128((uint32_t)((wm*64 + fm*16 + lrow)*128 + ki*32 + kseg*16));
                LDSM_X4(ahf[fm][0], ahf[fm][1], ahf[fm][2], ahf[fm][3], sbb + off);
                LDSM_X4(alf[fm][0], alf[fm][1], alf[fm][2], alf[fm][3], sbb + 16384u + off);
            }
            uint32_t bhf[4][2], blf[4][2];
            #pragma unroll
            for (int fp = 0; fp < 2; fp++) {
                uint32_t off = SWZ128((uint32_t)((wn*32 + fp*16 + nrow)*128 + ki*32 + ks2*16));
                LDSM_X4(bhf[fp*2][0], bhf[fp*2][1], bhf[fp*2+1][0], bhf[fp*2+1][1], sbb + 32768u + off);
                LDSM_X4(blf[fp*2][0], blf[fp*2][1], blf[fp*2+1][0], blf[fp*2+1][1], sbb + 49152u + off);
            }
            #pragma unroll
            for (int fm = 0; fm < 4; fm++)
            #pragma unroll
            for (int fn = 0; fn < 4; fn++) {
                mma16816(c[fm][fn], ahf[fm], bhf[fn]);
                mma16816(c[fm][fn], ahf[fm], blf[fn]);
                mma16816(c[fm][fn], alf[fm], bhf[fn]);
            }
        }
        __syncthreads();
    }

    const int l4 = lane >> 2;
    const int l2 = (lane & 3)*2;
    #pragma unroll
    for (int fm = 0; fm < 4; fm++) {
        const int mr0 = wm*64 + fm*16 + l4;
        #pragma unroll
        for (int fn = 0; fn < 4; fn++) {
            const int col = wn*32 + fn*8 + l2;
            if (MODE == 0) {
                const int gcol = blockIdx.y*128 + col;
                float2 bv = *(const float2*)(bias + blockIdx.z*768 + gcol);
                size_t m0 = (size_t)blockIdx.z*131072 + (size_t)blockIdx.x*128 + mr0;
                *(float2*)(outp + m0*768 + gcol)       = make_float2(c[fm][fn][0] + bv.x, c[fm][fn][1] + bv.y);
                *(float2*)(outp + (m0 + 8)*768 + gcol) = make_float2(c[fm][fn][2] + bv.x, c[fm][fn][3] + bv.y);
            } else {
                size_t m0 = (size_t)blockIdx.z*256 + (size_t)blockIdx.x*128 + mr0;
                *(float2*)(outp + m0*128 + col)       = make_float2(c[fm][fn][0], c[fm][fn][1]);
                *(float2*)(outp + (m0 + 8)*128 + col) = make_float2(c[fm][fn][2], c[fm][fn][3]);
            }
        }
    }
}

// ---------------- final reduce + MLP head ----------------
__global__ void __launch_bounds__(128) fc_reduce_kernel(
    const float* __restrict__ b1, const float* __restrict__ W2,
    const float* __restrict__ b2, float* __restrict__ out) {
    const int b = blockIdx.x;
    const int o = threadIdx.x;
    float s = b1[o];
    for (int t = 0; t < 512; t++)
        s += d_fc1p[((size_t)t*256 + b)*128 + o];
    float v = s > 0.f ? s : 0.01f*s;
    float c = v * __ldg(W2 + o);
    __shared__ float red[128];
    red[o] = c;
    __syncthreads();
    for (int st = 64; st > 0; st >>= 1) {
        if (o < st) red[o] += red[o + st];
        __syncthreads();
    }
    if (o == 0) out[b] = 1.f/(1.f + expf(-(red[0] + b2[0])));
}

// ---------------- launch ----------------
extern "C" void kernel_launch(void* const* d_in, const int* in_sizes, int n_in,
                              void* d_out, int out_size) {
    const int*   inputs = (const int*)  d_in[0];
    const float* emb    = (const float*)d_in[1];
    const float* wih0   = (const float*)d_in[2];
    const float* whh0   = (const float*)d_in[3];
    const float* bih0   = (const float*)d_in[4];
    const float* bhh0   = (const float*)d_in[5];
    const float* wih1   = (const float*)d_in[6];
    const float* whh1   = (const float*)d_in[7];
    const float* bih1   = (const float*)d_in[8];
    const float* bhh1   = (const float*)d_in[9];
    const float* W1     = (const float*)d_in[10];
    const float* b1     = (const float*)d_in[11];
    const float* W2     = (const float*)d_in[12];
    const float* b2     = (const float*)d_in[13];
    float* out = (float*)d_out;

    cudaFuncSetAttribute((const void*)rec_mma_kernel<0>,
                         cudaFuncAttributeMaxDynamicSharedMemorySize, RECM_SMEM);
    cudaFuncSetAttribute((const void*)rec_mma_kernel<1>,
                         cudaFuncAttributeMaxDynamicSharedMemorySize, RECM_SMEM);
    cudaFuncSetAttribute((const void*)mma_gemm_kernel<0>,
                         cudaFuncAttributeMaxDynamicSharedMemorySize, MMA_DSMEM);
    cudaFuncSetAttribute((const void*)mma_gemm_kernel<1>,
                         cudaFuncAttributeMaxDynamicSharedMemorySize, MMA_DSMEM);

    __nv_bfloat16 *h1hi, *h1lo, *h2hi, *h2lo, *wihhi, *wihlo, *W1hi, *W1lo;
    cudaGetSymbolAddress((void**)&h1hi, d_h1hi);
    cudaGetSymbolAddress((void**)&h1lo, d_h1lo);
    cudaGetSymbolAddress((void**)&h2hi, d_h2hi);
    cudaGetSymbolAddress((void**)&h2lo, d_h2lo);
    cudaGetSymbolAddress((void**)&wihhi, d_wihhi);
    cudaGetSymbolAddress((void**)&wihlo, d_wihlo);
    cudaGetSymbolAddress((void**)&W1hi, d_W1hi);
    cudaGetSymbolAddress((void**)&W1lo, d_W1lo);
    float *h1p, *h2p, *xp1p, *fc1p;
    cudaGetSymbolAddress((void**)&h1p, d_h1);
    cudaGetSymbolAddress((void**)&h2p, d_h2);
    cudaGetSymbolAddress((void**)&xp1p, d_xp1);
    cudaGetSymbolAddress((void**)&fc1p, d_fc1p);

    proj0_kernel<<<130, 256>>>(emb, wih0, bih0);
    split_kernel<<<768, 256>>>(wih1, wihhi, wihlo, 196608);
    split_kernel<<<4096, 256>>>(W1, W1hi, W1lo, 8388608);
    reset_bar_kernel<<<1, 512>>>();
    rec_mma_kernel<0><<<128, 256, RECM_SMEM>>>(inputs, whh0, bhh0);
    split_kernel<<<4096, 256>>>(h1p, h1hi, h1lo, 16777216);
    mma_gemm_kernel<0><<<dim3(1024, 6, 2), 256, MMA_DSMEM>>>(h1hi, h1lo, wihhi, wihlo, bih1, xp1p);
    reset_bar_kernel<<<1, 512>>>();
    rec_mma_kernel<1><<<128, 256, RECM_SMEM>>>(inputs, whh1, bhh1);
    split_kernel<<<4096, 256>>>(h2p, h2hi, h2lo, 16777216);
    mma_gemm_kernel<1><<<dim3(2, 1, 512), 256, MMA_DSMEM>>>(h2hi, h2lo, W1hi, W1lo, nullptr, fc1p);
    fc_reduce_kernel<<<256, 128>>>(b1, W2, b2, out);
}

// round 9
// speedup vs baseline: 2.8787x; 1.4503x over previous
#include <cuda_runtime.h>
#include <cuda_bf16.h>
#include <math.h>
#include <stddef.h>
#include <stdint.h>

// B=256, T=512, V=64(65 rows), E=128, H=256, 3H=768, D=2

// ---------------- PTX helpers (baseline ISA only: sm_80-era, safe on sm_103) ----------------
__device__ __forceinline__ uint32_t smem_to_u32(const void* p) {
    uint32_t a;
    asm("{ .reg .u64 t; cvta.to.shared.u64 t, %1; cvt.u32.u64 %0, t; }" : "=r"(a) : "l"(p));
    return a;
}
__device__ __forceinline__ void cp16(uint32_t s, const void* g) {
    asm volatile("cp.async.cg.shared.global [%0], [%1], 16;" :: "r"(s), "l"(g) : "memory");
}
#define CP_COMMIT() asm volatile("cp.async.commit_group;" ::: "memory")
#define CP_WAIT(n)  asm volatile("cp.async.wait_group %0;" :: "n"(n) : "memory")
#define LDSM_X4(r0, r1, r2, r3, addr) \
    asm volatile("ldmatrix.sync.aligned.m8n8.x4.shared.b16 {%0,%1,%2,%3}, [%4];" \
        : "=r"(r0), "=r"(r1), "=r"(r2), "=r"(r3) : "r"(addr))
#define LDSM_X2(r0, r1, addr) \
    asm volatile("ldmatrix.sync.aligned.m8n8.x2.shared.b16 {%0,%1}, [%2];" \
        : "=r"(r0), "=r"(r1) : "r"(addr))

__device__ __forceinline__ void mma16816(float* c, const uint32_t* a, const uint32_t* b) {
    asm volatile(
        "mma.sync.aligned.m16n8k16.row.col.f32.bf16.bf16.f32 "
        "{%0,%1,%2,%3}, {%4,%5,%6,%7}, {%8,%9}, {%0,%1,%2,%3};"
        : "+f"(c[0]), "+f"(c[1]), "+f"(c[2]), "+f"(c[3])
        : "r"(a[0]), "r"(a[1]), "r"(a[2]), "r"(a[3]), "r"(b[0]), "r"(b[1]));
}

#define SWZ128(b) ((b) ^ (((b) >> 3) & 0x70))

// pack 4 floats -> hi/lo bf16 pairs (8 bytes each)
__device__ __forceinline__ void split4(float4 v, uint2& hi, uint2& lo) {
    __nv_bfloat16 a0 = __float2bfloat16(v.x), a1 = __float2bfloat16(v.y);
    __nv_bfloat16 a2 = __float2bfloat16(v.z), a3 = __float2bfloat16(v.w);
    __nv_bfloat16 l0 = __float2bfloat16(v.x - __bfloat162float(a0));
    __nv_bfloat16 l1 = __float2bfloat16(v.y - __bfloat162float(a1));
    __nv_bfloat16 l2 = __float2bfloat16(v.z - __bfloat162float(a2));
    __nv_bfloat16 l3 = __float2bfloat16(v.w - __bfloat162float(a3));
    __nv_bfloat162 h01 = __halves2bfloat162(a0, a1), h23 = __halves2bfloat162(a2, a3);
    __nv_bfloat162 m01 = __halves2bfloat162(l0, l1), m23 = __halves2bfloat162(l2, l3);
    hi.x = *(uint32_t*)&h01; hi.y = *(uint32_t*)&h23;
    lo.x = *(uint32_t*)&m01; lo.y = *(uint32_t*)&m23;
}

__device__ __forceinline__ float fsig(float x) {
    return __fdividef(1.f, 1.f + __expf(-x));
}
__device__ __forceinline__ float ftanh(float x) {
    return __fdividef(2.f, 1.f + __expf(-2.f*x)) - 1.f;
}

// ---------------- static scratch ----------------
__device__ float d_ptab [2*65*768];
__device__ float d_xp1  [2*512*256*768];
__device__ float d_fc1p [512*256*128];
__device__ __nv_bfloat16 d_hpinghi[2*2*256*256];
__device__ __nv_bfloat16 d_hpinglo[2*2*256*256];
__device__ __nv_bfloat16 d_h1hi[67108864], d_h1lo[67108864];
__device__ __nv_bfloat16 d_h2hi[67108864], d_h2lo[67108864];
__device__ __nv_bfloat16 d_wihhi[786432], d_wihlo[786432];
__device__ __nv_bfloat16 d_W1hi[33554432], d_W1lo[33554432];
__device__ unsigned d_flags[4096];   // [16 groups][8 slots][32 pad]

__global__ void reset_bar_kernel() {
    d_flags[blockIdx.x*256 + threadIdx.x] = 0u;
}

// consumer-side poll: all warps poll the 8 peer flags of their group
__device__ __forceinline__ void poll_group(int gid, unsigned target, int lane) {
    if (lane < 8) {
        const unsigned* f = d_flags + (gid*8 + lane)*32;
        unsigned v;
        while (true) {
            asm volatile("ld.global.acquire.gpu.u32 %0, [%1];" : "=r"(v) : "l"(f));
            if (v >= target) break;
            __nanosleep(20);
        }
    }
    __syncwarp();
}

// ---------------- L0 proj table ----------------
__global__ void __launch_bounds__(256) proj0_kernel(const float* __restrict__ emb,
                                                    const float* __restrict__ wih,
                                                    const float* __restrict__ bih) {
    const int d = blockIdx.x / 65;
    const int v = blockIdx.x % 65;
    __shared__ float es[128];
    if (threadIdx.x < 128) es[threadIdx.x] = emb[v*128 + threadIdx.x];
    __syncthreads();
    for (int g = threadIdx.x; g < 768; g += 256) {
        const float* w = wih + ((size_t)d*768 + g)*128;
        float s = bih[d*768 + g];
        #pragma unroll 4
        for (int e = 0; e < 128; e++) s += es[e]*__ldg(w + e);
        d_ptab[((size_t)d*65 + v)*768 + g] = s;
    }
}

// ---------------- fp32 -> bf16 hi/lo split (weights only now) ----------------
__global__ void __launch_bounds__(256) split_kernel(const float* __restrict__ x,
        __nv_bfloat16* __restrict__ hi, __nv_bfloat16* __restrict__ lo, size_t n4) {
    size_t i = (size_t)blockIdx.x*256 + threadIdx.x;
    size_t stride = (size_t)gridDim.x*256;
    for (; i < n4; i += stride) {
        float4 v = __ldg((const float4*)x + i);
        uint2 h, l;
        split4(v, h, l);
        ((uint2*)hi)[i] = h;
        ((uint2*)lo)[i] = l;
    }
}

// ---------------- MMA recurrence (both layers) ----------------
// 128 CTAs = dir(2) x batch-slice(8 x 32 rows) x unit-slice(8 x 32 units)
// Per step: G[32 x 96] = h[32 x 256] @ Wslice[96 x 256]^T via split-bf16 3-pass mma.
// h exchanged between the 8 CTAs of a group as pre-split bf16 hi/lo through L2,
// synced by per-CTA step-counter flags (release/acquire), received via cp.async.
// SMEM layout (1024-aligned base):
//   WHI  @ 0      : 4 chunks x (96 rows x 128B)   = 49152
//   WLO  @ 49152  : 49152
//   HHI  @ 98304  : 4 chunks x (32 rows x 128B)   = 16384
//   HLO  @ 114688 : 16384
//   G    @ 131072 : 32 x 100 floats               = 12800
//   HPREV@ 143872 : 32 x 36 floats                = 4608
#define RECM_SMEM (148480 + 1024)

template<int LAYER>
__global__ void __launch_bounds__(256, 1) rec_mma_kernel(
    const int* __restrict__ inputs,
    const float* __restrict__ w_hh,
    const float* __restrict__ b_hh) {
    extern __shared__ char sm_raw[];
    __shared__ float bhh_s[96];
    const uint32_t raw  = smem_to_u32(sm_raw);
    const uint32_t base = (raw + 1023u) & ~1023u;
    char* sb = sm_raw + (base - raw);
    float* Gs    = (float*)(sb + 131072);
    float* Hprev = (float*)(sb + 143872);

    const int bid = blockIdx.x;
    const int dir = bid >> 6;
    const int rem = bid & 63;
    const int bs  = rem >> 3;
    const int us  = rem & 7;
    const int b0  = bs * 32;
    const int j0  = us * 32;
    const int gid = dir*8 + bs;
    const int tid = threadIdx.x;
    const int lane = tid & 31;
    const int wid  = tid >> 5;

    // ---- one-time: W_hh slice -> bf16 hi/lo swizzled smem (gate-interleaved rows) ----
    {
        const int k0 = (tid & 7) * 32;
        #pragma unroll
        for (int rr = 0; rr < 3; rr++) {
            const int lr = rr*32 + (tid >> 3);
            const int g  = lr >> 5;
            const float* src = w_hh + ((size_t)dir*768 + g*256 + j0 + (lr & 31))*256 + k0;
            const uint32_t cb = (uint32_t)(k0 >> 6)*12288u + (uint32_t)lr*128u + (uint32_t)(k0 & 63)*2u;
            #pragma unroll
            for (int q = 0; q < 8; q++) {
                float4 v = __ldg((const float4*)src + q);
                uint2 h, l;
                split4(v, h, l);
                uint32_t off = SWZ128(cb + q*8);
                *(uint2*)(sb + off)          = h;
                *(uint2*)(sb + 49152u + off) = l;
            }
        }
    }
    if (tid < 96) bhh_s[tid] = b_hh[dir*768 + (tid>>5)*256 + j0 + (tid & 31)];
    // zero h tiles + hprev
    for (int i = tid; i < 2048; i += 256)
        ((uint4*)(sb + 98304))[i] = make_uint4(0,0,0,0);
    for (int i = tid; i < 1152; i += 256)
        Hprev[i] = 0.f;
    __syncthreads();

    // per-thread nonlinearity mapping
    const int bb = tid >> 3;
    const int ju = (tid & 7) * 4;
    const int bg = b0 + bb;

    // MMA lane mappings
    const int wm = wid >> 2, wn = wid & 3;
    const int lrow = lane & 15, kseg = lane >> 4;
    const int g8 = lane >> 3, lr8 = lane & 7;
    const int nrx4 = ((g8 >> 1) & 1)*8 + lr8;
    const int ksx4 = g8 & 1;
    const int lx = lane & 15;
    const int rowb2 = lx & 7, kh2 = (lx >> 3) & 1;

    __nv_bfloat16* obh = (LAYER == 0) ? d_h1hi : d_h2hi;
    __nv_bfloat16* obl = (LAYER == 0) ? d_h1lo : d_h2lo;

    for (int s_ = 0; s_ < 512; s_++) {
        // prefetch x-projections (independent of peers -> issue before poll)
        const int t_in = (dir == 0) ? s_ : (511 - s_);
        float4 xr4, xz4, xn4;
        if (LAYER == 0) {
            const int tok = __ldg(inputs + bg*512 + t_in);
            const float* pt = d_ptab + ((size_t)dir*65 + tok)*768 + j0 + ju;
            xr4 = __ldg((const float4*)(pt));
            xz4 = __ldg((const float4*)(pt + 256));
            xn4 = __ldg((const float4*)(pt + 512));
        } else {
            const float* xp = d_xp1 + ((size_t)dir*131072 + (size_t)t_in*256 + bg)*768 + j0 + ju;
            xr4 = __ldg((const float4*)(xp));
            xz4 = __ldg((const float4*)(xp + 256));
            xn4 = __ldg((const float4*)(xp + 512));
        }

        if (s_ > 0) {
            poll_group(gid, (unsigned)s_, lane);
            const int par = s_ & 1;
            const __nv_bfloat16* ghi = d_hpinghi + (((size_t)dir*2 + par)*256 + b0)*256;
            const __nv_bfloat16* glo = d_hpinglo + (((size_t)dir*2 + par)*256 + b0)*256;
            #pragma unroll
            for (int v = 0; v < 4; v++) {
                int vv = tid + v*256;          // 0..1023
                int r   = vv >> 5;             // 0..31 (batch row)
                int ks16 = vv & 31;            // 16B segment (8 bf16)
                uint32_t dst = SWZ128((uint32_t)((ks16 >> 3)*4096 + r*128 + (ks16 & 7)*16));
                size_t gofs = (size_t)r*256 + (size_t)ks16*8;
                cp16(base + 98304u  + dst, ghi + gofs);
                cp16(base + 114688u + dst, glo + gofs);
            }
            CP_COMMIT(); CP_WAIT(0);
            __syncthreads();
        }

        // ---- MMA: G = h @ Wslice^T, 3-pass split ----
        float c[3][4];
        #pragma unroll
        for (int fn = 0; fn < 3; fn++)
            #pragma unroll
            for (int q = 0; q < 4; q++) c[fn][q] = 0.f;

        #pragma unroll
        for (int ks = 0; ks < 16; ks++) {
            const int ck = ks >> 2, ki = ks & 3;
            const uint32_t ain = base + 98304u + (uint32_t)ck*4096u +
                SWZ128((uint32_t)((wm*16 + lrow)*128 + ki*32 + kseg*16));
            uint32_t ah[4], al[4];
            LDSM_X4(ah[0], ah[1], ah[2], ah[3], ain);
            LDSM_X4(al[0], al[1], al[2], al[3], ain + 16384u);
            const uint32_t bcb = base + (uint32_t)ck*12288u;
            const uint32_t b4 = bcb +
                SWZ128((uint32_t)((wn*24 + nrx4)*128 + ki*32 + ksx4*16));
            const uint32_t b2 = bcb +
                SWZ128((uint32_t)((wn*24 + 16 + rowb2)*128 + ki*32 + kh2*16));
            uint32_t bh[3][2], bl[3][2];
            LDSM_X4(bh[0][0], bh[0][1], bh[1][0], bh[1][1], b4);
            LDSM_X2(bh[2][0], bh[2][1], b2);
            LDSM_X4(bl[0][0], bl[0][1], bl[1][0], bl[1][1], b4 + 49152u);
            LDSM_X2(bl[2][0], bl[2][1], b2 + 49152u);
            #pragma unroll
            for (int fn = 0; fn < 3; fn++) {
                mma16816(c[fn], ah, bh[fn]);
                mma16816(c[fn], ah, bl[fn]);
                mma16816(c[fn], al, bh[fn]);
            }
        }

        // write G to smem
        {
            const int l4 = lane >> 2, l2 = (lane & 3)*2;
            #pragma unroll
            for (int fn = 0; fn < 3; fn++) {
                const int col = wn*24 + fn*8 + l2;
                *(float2*)&Gs[(wm*16 + l4)*100 + col]     = make_float2(c[fn][0], c[fn][1]);
                *(float2*)&Gs[(wm*16 + l4 + 8)*100 + col] = make_float2(c[fn][2], c[fn][3]);
            }
        }
        __syncthreads();

        // ---- nonlinearity + h update ----
        {
            float4 gr = *(const float4*)&Gs[bb*100 + ju];
            float4 gz = *(const float4*)&Gs[bb*100 + 32 + ju];
            float4 gn = *(const float4*)&Gs[bb*100 + 64 + ju];
            float4 hp = *(const float4*)&Hprev[bb*36 + ju];
            float hn[4];
            const float* xr = &xr4.x;
            const float* xz = &xz4.x;
            const float* xn = &xn4.x;
            const float* grp = &gr.x;
            const float* gzp = &gz.x;
            const float* gnp = &gn.x;
            const float* hpp = &hp.x;
            #pragma unroll
            for (int i = 0; i < 4; i++) {
                float r = fsig(xr[i] + grp[i] + bhh_s[     ju + i]);
                float z = fsig(xz[i] + gzp[i] + bhh_s[32 + ju + i]);
                float n = ftanh(xn[i] + r*(gnp[i] + bhh_s[64 + ju + i]));
                hn[i] = (1.f - z)*n + z*hpp[i];
            }
            float4 hv = make_float4(hn[0], hn[1], hn[2], hn[3]);
            *(float4*)&Hprev[bb*36 + ju] = hv;
            uint2 hhi, hlo;
            split4(hv, hhi, hlo);
            size_t oo = ((size_t)t_in*256 + bg)*512 + (size_t)dir*256 + j0 + ju;
            *(uint2*)(obh + oo) = hhi;
            *(uint2*)(obl + oo) = hlo;
            if (s_ != 511) {
                size_t po = (((size_t)dir*2 + ((s_+1) & 1))*256 + bg)*256 + j0 + ju;
                asm volatile("st.global.cg.v2.u32 [%0], {%1,%2};" :: "l"(d_hpinghi + po), "r"(hhi.x), "r"(hhi.y));
                asm volatile("st.global.cg.v2.u32 [%0], {%1,%2};" :: "l"(d_hpinglo + po), "r"(hlo.x), "r"(hlo.y));
            }
        }
        if (s_ != 511) {
            __threadfence();
            __syncthreads();
            if (tid == 0) {
                asm volatile("st.global.cg.u32 [%0], %1;"
                    :: "l"(d_flags + (gid*8 + us)*32), "r"((unsigned)(s_ + 1)));
            }
        }
    }
}

// ---------------- split-bf16 warp-MMA GEMM (mma.sync m16n8k16 bf16) ----------------
// MODE 0: xp1 = h1 @ wih1^T + bias.  grid (1024 mtiles, 6 ntiles, 2 dirs)
// MODE 1: fc1 partials per t.        grid (2 mtiles, 1, 512 t)
#define MMA_DSMEM (2*65536 + 1024)

template<int MODE>
__global__ void __launch_bounds__(256) mma_gemm_kernel(
    const __nv_bfloat16* __restrict__ Ah, const __nv_bfloat16* __restrict__ Al,
    const __nv_bfloat16* __restrict__ Bh, const __nv_bfloat16* __restrict__ Bl,
    const float* __restrict__ bias, float* __restrict__ outp) {
    extern __shared__ char dsm_raw[];
    const uint32_t raw  = smem_to_u32(dsm_raw);
    const uint32_t base = (raw + 1023u) & ~1023u;

    const int tid  = threadIdx.x;
    const int lane = tid & 31;
    const int wid  = tid >> 5;
    const int wm   = wid >> 2;
    const int wn   = wid & 3;

    size_t arow0, brow0, bstride, bk0;
    if (MODE == 0) {
        arow0 = (size_t)blockIdx.x * 128;
        brow0 = (size_t)blockIdx.z * 768 + (size_t)blockIdx.y * 128;
        bstride = 512; bk0 = 0;
    } else {
        arow0 = (size_t)blockIdx.z * 256 + (size_t)blockIdx.x * 128;
        brow0 = 0;
        bstride = 262144; bk0 = (size_t)blockIdx.z * 512;
    }

    float c[4][4][4];
    #pragma unroll
    for (int fm = 0; fm < 4; fm++)
    #pragma unroll
    for (int fn = 0; fn < 4; fn++)
    #pragma unroll
    for (int q = 0; q < 4; q++) c[fm][fn][q] = 0.f;

    auto issue = [&](int kc, int buf) {
        const uint32_t sbb = base + (uint32_t)buf*65536u;
        #pragma unroll
        for (int v = 0; v < 4; v++) {
            int vv = tid + v*256;
            int r = vv >> 3, seg = vv & 7;
            uint32_t sw = SWZ128((uint32_t)(r*128 + seg*16));
            size_t k  = (size_t)kc*64 + (size_t)seg*8;
            size_t ga = (arow0 + r)*512 + k;
            size_t gb = (brow0 + r)*bstride + bk0 + k;
            cp16(sbb +          sw, Ah + ga);
            cp16(sbb + 16384u + sw, Al + ga);
            cp16(sbb + 32768u + sw, Bh + gb);
            cp16(sbb + 49152u + sw, Bl + gb);
        }
    };

    issue(0, 0); CP_COMMIT();

    for (int kc = 0; kc < 8; kc++) {
        if (kc < 7) {
            issue(kc + 1, (kc + 1) & 1); CP_COMMIT();
            CP_WAIT(1);
        } else {
            CP_WAIT(0);
        }
        __syncthreads();

        const uint32_t sbb = base + (uint32_t)(kc & 1)*65536u;
        const int lrow = lane & 15, kseg = lane >> 4;
        const int g = lane >> 3, lr = lane & 7;
        const int nrow = ((g >> 1) & 1)*8 + lr;
        const int ks2 = g & 1;

        #pragma unroll
        for (int ki = 0; ki < 4; ki++) {
            uint32_t ahf[4][4], alf[4][4];
            #pragma unroll
            for (int fm = 0; fm < 4; fm++) {
                uint32_t off = SWZ128((uint32_t)((wm*64 + fm*16 + lrow)*128 + ki*32 + kseg*16));
                LDSM_X4(ahf[fm][0], ahf[fm][1], ahf[fm][2], ahf[fm][3], sbb + off);
                LDSM_X4(alf[fm][0], alf[fm][1], alf[fm][2], alf[fm][3], sbb + 16384u + off);
            }
            uint32_t bhf[4][2], blf[4][2];
            #pragma unroll
            for (int fp = 0; fp < 2; fp++) {
                uint32_t off = SWZ128((uint32_t)((wn*32 + fp*16 + nrow)*128 + ki*32 + ks2*16));
                LDSM_X4(bhf[fp*2][0], bhf[fp*2][1], bhf[fp*2+1][0], bhf[fp*2+1][1], sbb + 32768u + off);
                LDSM_X4(blf[fp*2][0], blf[fp*2][1], blf[fp*2+1][0], blf[fp*2+1][1], sbb + 49152u + off);
            }
            #pragma unroll
            for (int fm = 0; fm < 4; fm++)
            #pragma unroll
            for (int fn = 0; fn < 4; fn++) {
                mma16816(c[fm][fn], ahf[fm], bhf[fn]);
                mma16816(c[fm][fn], ahf[fm], blf[fn]);
                mma16816(c[fm][fn], alf[fm], bhf[fn]);
            }
        }
        __syncthreads();
    }

    const int l4 = lane >> 2;
    const int l2 = (lane & 3)*2;
    #pragma unroll
    for (int fm = 0; fm < 4; fm++) {
        const int mr0 = wm*64 + fm*16 + l4;
        #pragma unroll
        for (int fn = 0; fn < 4; fn++) {
            const int col = wn*32 + fn*8 + l2;
            if (MODE == 0) {
                const int gcol = blockIdx.y*128 + col;
                float2 bv = *(const float2*)(bias + blockIdx.z*768 + gcol);
                size_t m0 = (size_t)blockIdx.z*131072 + (size_t)blockIdx.x*128 + mr0;
                *(float2*)(outp + m0*768 + gcol)       = make_float2(c[fm][fn][0] + bv.x, c[fm][fn][1] + bv.y);
                *(float2*)(outp + (m0 + 8)*768 + gcol) = make_float2(c[fm][fn][2] + bv.x, c[fm][fn][3] + bv.y);
            } else {
                size_t m0 = (size_t)blockIdx.z*256 + (size_t)blockIdx.x*128 + mr0;
                *(float2*)(outp + m0*128 + col)       = make_float2(c[fm][fn][0], c[fm][fn][1]);
                *(float2*)(outp + (m0 + 8)*128 + col) = make_float2(c[fm][fn][2], c[fm][fn][3]);
            }
        }
    }
}

// ---------------- final reduce + MLP head ----------------
__global__ void __launch_bounds__(128) fc_reduce_kernel(
    const float* __restrict__ b1, const float* __restrict__ W2,
    const float* __restrict__ b2, float* __restrict__ out) {
    const int b = blockIdx.x;
    const int o = threadIdx.x;
    float s = b1[o];
    for (int t = 0; t < 512; t++)
        s += d_fc1p[((size_t)t*256 + b)*128 + o];
    float v = s > 0.f ? s : 0.01f*s;
    float c = v * __ldg(W2 + o);
    __shared__ float red[128];
    red[o] = c;
    __syncthreads();
    for (int st = 64; st > 0; st >>= 1) {
        if (o < st) red[o] += red[o + st];
        __syncthreads();
    }
    if (o == 0) out[b] = 1.f/(1.f + expf(-(red[0] + b2[0])));
}

// ---------------- launch ----------------
extern "C" void kernel_launch(void* const* d_in, const int* in_sizes, int n_in,
                              void* d_out, int out_size) {
    const int*   inputs = (const int*)  d_in[0];
    const float* emb    = (const float*)d_in[1];
    const float* wih0   = (const float*)d_in[2];
    const float* whh0   = (const float*)d_in[3];
    const float* bih0   = (const float*)d_in[4];
    const float* bhh0   = (const float*)d_in[5];
    const float* wih1   = (const float*)d_in[6];
    const float* whh1   = (const float*)d_in[7];
    const float* bih1   = (const float*)d_in[8];
    const float* bhh1   = (const float*)d_in[9];
    const float* W1     = (const float*)d_in[10];
    const float* b1     = (const float*)d_in[11];
    const float* W2     = (const float*)d_in[12];
    const float* b2     = (const float*)d_in[13];
    float* out = (float*)d_out;

    cudaFuncSetAttribute((const void*)rec_mma_kernel<0>,
                         cudaFuncAttributeMaxDynamicSharedMemorySize, RECM_SMEM);
    cudaFuncSetAttribute((const void*)rec_mma_kernel<1>,
                         cudaFuncAttributeMaxDynamicSharedMemorySize, RECM_SMEM);
    cudaFuncSetAttribute((const void*)mma_gemm_kernel<0>,
                         cudaFuncAttributeMaxDynamicSharedMemorySize, MMA_DSMEM);
    cudaFuncSetAttribute((const void*)mma_gemm_kernel<1>,
                         cudaFuncAttributeMaxDynamicSharedMemorySize, MMA_DSMEM);

    __nv_bfloat16 *h1hi, *h1lo, *h2hi, *h2lo, *wihhi, *wihlo, *W1hi, *W1lo;
    cudaGetSymbolAddress((void**)&h1hi, d_h1hi);
    cudaGetSymbolAddress((void**)&h1lo, d_h1lo);
    cudaGetSymbolAddress((void**)&h2hi, d_h2hi);
    cudaGetSymbolAddress((void**)&h2lo, d_h2lo);
    cudaGetSymbolAddress((void**)&wihhi, d_wihhi);
    cudaGetSymbolAddress((void**)&wihlo, d_wihlo);
    cudaGetSymbolAddress((void**)&W1hi, d_W1hi);
    cudaGetSymbolAddress((void**)&W1lo, d_W1lo);
    float *xp1p, *fc1p;
    cudaGetSymbolAddress((void**)&xp1p, d_xp1);
    cudaGetSymbolAddress((void**)&fc1p, d_fc1p);

    proj0_kernel<<<130, 256>>>(emb, wih0, bih0);
    split_kernel<<<768, 256>>>(wih1, wihhi, wihlo, 196608);
    split_kernel<<<4096, 256>>>(W1, W1hi, W1lo, 8388608);
    reset_bar_kernel<<<16, 256>>>();
    rec_mma_kernel<0><<<128, 256, RECM_SMEM>>>(inputs, whh0, bhh0);
    mma_gemm_kernel<0><<<dim3(1024, 6, 2), 256, MMA_DSMEM>>>(h1hi, h1lo, wihhi, wihlo, bih1, xp1p);
    reset_bar_kernel<<<16, 256>>>();
    rec_mma_kernel<1><<<128, 256, RECM_SMEM>>>(inputs, whh1, bhh1);
    mma_gemm_kernel<1><<<dim3(2, 1, 512), 256, MMA_DSMEM>>>(h2hi, h2lo, W1hi, W1lo, nullptr, fc1p);
    fc_reduce_kernel<<<256, 128>>>(b1, W2, b2, out);
}